// round 8
// baseline (speedup 1.0000x reference)
#include <cuda_runtime.h>
#include <cuda_fp16.h>

// feature_map [512,512,64] f32, boxes [512,4] f32 (cx,cy,w,h), out [512,32,32,64] f32
#define IN_H    512
#define IN_W    512
#define NC4     16          // channels as 4-channel groups
#define NBOX    512
#define OUTW    32
#define OYT     4           // oy rows per CTA tile (was 8; cut for regs/occupancy)
#define NTILES  (OUTW / OYT)
#define MAXTAPS 36          // ks < 16  ->  taps <= 2*16+2 = 34
#define MAXROWS 88          // union of 4 oy windows: 3*inv + 2ks + 2 <= 82

typedef unsigned long long ull;

// fp16 staged copy of the feature map (32 MB device scratch; legal per rules).
__device__ uint2 g_fm16[IN_H * IN_W * NC4];

// ---- pre-pass: f32 -> fp16 conversion, fully coalesced ----
__global__ __launch_bounds__(1024)
void convert_kernel(const float* __restrict__ fm)
{
    int i = blockIdx.x * 1024 + threadIdx.x;   // one c4 group per thread
    const float4 v = ((const float4*)fm)[i];
    __half2 a = __floats2half2_rn(v.x, v.y);
    __half2 b = __floats2half2_rn(v.z, v.w);
    uint2 o;
    o.x = *reinterpret_cast<unsigned*>(&a);
    o.y = *reinterpret_cast<unsigned*>(&b);
    g_fm16[i] = o;
}

// half2 (packed in u32) -> f32x2 (packed in u64), lane order preserved
__device__ __forceinline__ ull h2_to_f32x2(unsigned h2)
{
    ull r;
    asm("{\n\t"
        ".reg .f16 a, b;\n\t"
        ".reg .f32 lo, hi;\n\t"
        "mov.b32 {a, b}, %1;\n\t"
        "cvt.f32.f16 lo, a;\n\t"
        "cvt.f32.f16 hi, b;\n\t"
        "mov.b64 %0, {lo, hi};\n\t"
        "}" : "=l"(r) : "r"(h2));
    return r;
}

// packed dual-FMA: acc.lane += v.lane * w.lane  (IEEE f32 per lane)
#define FMA2(acc, v, w) \
    asm("fma.rn.f32x2 %0, %1, %2, %0;" : "+l"(acc) : "l"(v), "l"(w))
#define ADD2(dst, a, b) \
    asm("add.rn.f32x2 %0, %1, %2;" : "=l"(dst) : "l"(a), "l"(b))

// One CTA per (box, oy-tile of 4). 512 threads = 32 ox x 16 c4 lanes.
// Each thread x-filters each union row once (fp16 loads, packed f32x2 math,
// dual even/odd accumulator chains for ILP), then scatters into 4 oy
// accumulator pairs with SMEM y-weights. 3 CTAs/SM for latency hiding.
// Weight math replicates jax.image.scale_and_translate(method="linear",
// antialias=True) exactly (formulas verified since R4).
__global__ __launch_bounds__(512, 3)
void roi_align_kernel(const float* __restrict__ boxes,
                      float* __restrict__ out)
{
    __shared__ float2 s_wx2[OUTW * MAXTAPS];    // x weights, duplicated {w,w}
    __shared__ int    s_xb[OUTW];               // x window base per ox
    __shared__ float  s_sy[OYT];                // y sample pos per tile oy
    __shared__ float  s_invn[OYT];              // y norm (0 if invalid)
    __shared__ int    s_yb[OYT];                // y window base per tile oy
    __shared__ float2 s_wyt2[MAXROWS * OYT];    // y weights, duplicated {w,w}

    const int tile = blockIdx.x;   // 0..7
    const int box  = blockIdx.y;   // 0..511
    const int tid  = threadIdx.x;

    // ---- box parameters (all threads) ----
    const float4 b = ((const float4*)boxes)[box];
    float x0 = b.x - b.z * 0.5f;           // pre-clamp w/h (reference order)
    float y0 = b.y - b.w * 0.5f;
    float bw = fmaxf(b.z, 1e-6f);
    float bh = fmaxf(b.w, 1e-6f);

    float scale_x = 32.0f / (bw * 512.0f);
    float inv_x   = 1.0f / scale_x;
    float ks_x    = fmaxf(inv_x, 1.0f);
    float toff_x  = ((-x0 * 32.0f) / bw) * inv_x;
    int   ntx     = min((int)(2.0f * ks_x) + 2, MAXTAPS);

    float scale_y = 32.0f / (bh * 512.0f);
    float inv_y   = 1.0f / scale_y;
    float ks_y    = fmaxf(inv_y, 1.0f);
    float toff_y  = ((-y0 * 32.0f) / bh) * inv_y;
    int   nty     = min((int)(2.0f * ks_y) + 2, MAXTAPS);
    float rks_y   = 1.0f / ks_y;

    // ---- phase 1: per-ox x weights (threads 0..31), per-oy y params (32..35)
    if (tid < OUTW) {
        const int ox = tid;
        float s    = ((float)ox + 0.5f) * inv_x - toff_x - 0.5f;
        int   base = min(max((int)ceilf(s - ks_x), 0), IN_W - ntx);
        float rks  = 1.0f / ks_x;
        float norm = 0.0f;
        for (int j = 0; j < ntx; j++)
            norm += fmaxf(0.0f, 1.0f - fabsf(s - (float)(base + j)) * rks);
        bool valid = (s >= -0.5f) && (s <= (float)IN_W - 0.5f)
                     && (fabsf(norm) > 1.1920929e-4f);   // 1000 * eps_f32
        float invn = valid ? (1.0f / norm) : 0.0f;
        for (int j = 0; j < ntx; j++) {
            float w = fmaxf(0.0f, 1.0f - fabsf(s - (float)(base + j)) * rks) * invn;
            s_wx2[ox * MAXTAPS + j] = make_float2(w, w);
        }
        s_xb[ox] = base;
    } else if (tid < OUTW + OYT) {
        const int k  = tid - OUTW;
        const int oy = tile * OYT + k;
        float sy = ((float)oy + 0.5f) * inv_y - toff_y - 0.5f;
        int   yb = min(max((int)ceilf(sy - ks_y), 0), IN_H - nty);
        float norm = 0.0f;
        for (int j = 0; j < nty; j++)
            norm += fmaxf(0.0f, 1.0f - fabsf(sy - (float)(yb + j)) * rks_y);
        bool valid = (sy >= -0.5f) && (sy <= (float)IN_H - 0.5f)
                     && (fabsf(norm) > 1.1920929e-4f);
        s_sy[k]   = sy;
        s_invn[k] = valid ? (1.0f / norm) : 0.0f;
        s_yb[k]   = yb;
    }
    __syncthreads();

    // ---- phase 2: fill duplicated wy table over the row union ----
    const int rmin   = s_yb[0];                       // sy monotone in k
    const int rcount = s_yb[OYT - 1] + nty - rmin;    // <= 82
    for (int idx = tid; idx < rcount * OYT; idx += 512) {
        int r = idx >> 2, k = idx & (OYT - 1);
        float w = fmaxf(0.0f, 1.0f - fabsf(s_sy[k] - (float)(rmin + r)) * rks_y)
                  * s_invn[k];
        s_wyt2[idx] = make_float2(w, w);
    }
    __syncthreads();

    // active rows form one interval (y-windows of the 4 oy overlap)
    const int rlo = max(rmin, (int)ceilf(s_sy[0] - ks_y));
    const int rhi = min(rmin + rcount, (int)floorf(s_sy[OYT - 1] + ks_y) + 1);

    // ---- main loop: thread = (ox, c4), 4 oy f32x2-pair accumulators ----
    const int ox = tid >> 4;
    const int c4 = tid & 15;
    const int xb = s_xb[ox];
    const ull* __restrict__ wxp = (const ull*)&s_wx2[ox * MAXTAPS];

    ull a01[OYT], a23[OYT];
    #pragma unroll
    for (int k = 0; k < OYT; k++) { a01[k] = 0ull; a23[k] = 0ull; }

    const uint2* __restrict__ rowp0 =
        g_fm16 + ((size_t)rlo * IN_W + xb) * NC4 + c4;

    for (int r = rlo; r < rhi; r++, rowp0 += IN_W * NC4) {
        // x convolution for this row: dual even/odd chains for ILP
        ull r01a = 0ull, r01b = 0ull, r23a = 0ull, r23b = 0ull;
        int j = 0;
        for (; j + 2 <= ntx; j += 2) {
            ull  w0 = wxp[j],      w1 = wxp[j + 1];
            uint2 v0 = rowp0[j * NC4];
            uint2 v1 = rowp0[(j + 1) * NC4];
            FMA2(r01a, h2_to_f32x2(v0.x), w0);
            FMA2(r23a, h2_to_f32x2(v0.y), w0);
            FMA2(r01b, h2_to_f32x2(v1.x), w1);
            FMA2(r23b, h2_to_f32x2(v1.y), w1);
        }
        if (j < ntx) {
            ull  w0 = wxp[j];
            uint2 v0 = rowp0[j * NC4];
            FMA2(r01a, h2_to_f32x2(v0.x), w0);
            FMA2(r23a, h2_to_f32x2(v0.y), w0);
        }
        ull r01, r23;
        ADD2(r01, r01a, r01b);
        ADD2(r23, r23a, r23b);

        // scatter into 4 oy accumulators (packed)
        const ull* __restrict__ wyp = (const ull*)&s_wyt2[(r - rmin) * OYT];
        #pragma unroll
        for (int k = 0; k < OYT; k++) {
            ull wy2 = wyp[k];
            FMA2(a01[k], r01, wy2);
            FMA2(a23[k], r23, wy2);
        }
    }

    // ---- write out[box][tile*4+k][ox][c] ----
    float2* __restrict__ out2 = (float2*)out;
    #pragma unroll
    for (int k = 0; k < OYT; k++) {
        int oy = tile * OYT + k;
        size_t base = ((((size_t)box * OUTW + oy) * OUTW + ox) * NC4 + c4) * 2;
        out2[base + 0] = *reinterpret_cast<float2*>(&a01[k]);
        out2[base + 1] = *reinterpret_cast<float2*>(&a23[k]);
    }
}

extern "C" void kernel_launch(void* const* d_in, const int* in_sizes, int n_in,
                              void* d_out, int out_size)
{
    const float* fm    = (const float*)d_in[0];   // [512, 512, 64] f32
    const float* boxes = (const float*)d_in[1];   // [512, 4] f32
    float* out = (float*)d_out;                   // [512, 32, 32, 64] f32

    // pre-pass: stage feature map as fp16 (16.7M elems / 4 per thread)
    convert_kernel<<<(IN_H * IN_W * NC4) / 1024, 1024>>>(fm);

    dim3 grid(NTILES, NBOX);   // (oy-tile, box) -> 4096 CTAs
    roi_align_kernel<<<grid, 512>>>(boxes, out);
}